// round 10
// baseline (speedup 1.0000x reference)
#include <cuda_runtime.h>
#include <cuda_bf16.h>
#include <math.h>

// ---------------- problem constants ----------------
#define BB   8
#define HSZ  64
#define WSZ  64
#define NSP  (HSZ*WSZ)          // 4096 spatial positions per batch
#define MR   (BB*NSP)           // 32768 rows
#define CC   512
#define TT   77
#define MT   (BB*TT)            // 616 text rows
#define HH8  8
#define DH64 64
#define FFN  2048

// ---------------- scratch (device globals; no runtime alloc) ----------------
__device__ float g_x  [(size_t)MR*CC];   // LN1 output
__device__ float g_q  [(size_t)MR*CC];   // q projection (l2-normed in place)
__device__ float g_kf [(size_t)MT*CC];
__device__ float g_vf [(size_t)MT*CC];
__device__ int   g_pad[MT];
__device__ float g_al [(size_t)MR*CC];   // attention output (pre-wo)
__device__ float g_o  [(size_t)MR*CC];   // aligned@wo + bo
__device__ float g_g  [(size_t)MR*CC];   // gate linear
__device__ float g_cf [(size_t)MR*HH8];  // per-head conf
__device__ float g_y  [(size_t)MR*CC];   // residual stream
__device__ float g_h  [(size_t)MR*CC];   // LN2 output
__device__ float g_f1 [(size_t)MR*FFN];  // ffn intermediate

// ---------------- helpers ----------------
__device__ __forceinline__ float warp_sum(float v){
#pragma unroll
    for (int o = 16; o > 0; o >>= 1) v += __shfl_xor_sync(0xffffffffu, v, o);
    return v;
}
__device__ __forceinline__ float warp_max(float v){
#pragma unroll
    for (int o = 16; o > 0; o >>= 1) v = fmaxf(v, __shfl_xor_sync(0xffffffffu, v, o));
    return v;
}
__device__ __forceinline__ float gelu_exact(float x){
    return 0.5f * x * (1.0f + erff(x * 0.70710678118654752440f));
}

// block of 128 threads: reduce two partial sums to totals (all threads get result)
__device__ __forceinline__ void block_reduce2_128(float& s, float& s2){
    __shared__ float sh[8];
    s  = warp_sum(s);
    s2 = warp_sum(s2);
    int t = threadIdx.x;
    if ((t & 31) == 0){ sh[t >> 5] = s; sh[4 + (t >> 5)] = s2; }
    __syncthreads();
    s  = sh[0] + sh[1] + sh[2] + sh[3];
    s2 = sh[4] + sh[5] + sh[6] + sh[7];
}

// ---------------- LayerNorm over 512 (one block per row, 128 threads) ----------------
__global__ void ln_kernel(const float* __restrict__ in, const float* __restrict__ w,
                          const float* __restrict__ b, float* __restrict__ out){
    int row = blockIdx.x, t = threadIdx.x;
    const float* p = in + (size_t)row * CC;
    float v[4], s = 0.f, s2 = 0.f;
#pragma unroll
    for (int i = 0; i < 4; i++){ float x = p[t + 128*i]; v[i] = x; s += x; s2 += x*x; }
    block_reduce2_128(s, s2);
    float mu  = s  * (1.0f/512.0f);
    float var = s2 * (1.0f/512.0f) - mu*mu;
    float rs  = rsqrtf(var + 1e-5f);
#pragma unroll
    for (int i = 0; i < 4; i++){
        int c = t + 128*i;
        out[(size_t)row*CC + c] = (v[i]-mu)*rs*w[c] + b[c];
    }
}

// ---------------- row-wise L2 normalize (in place) ----------------
__global__ void l2norm_kernel(float* __restrict__ p){
    int row = blockIdx.x, t = threadIdx.x;
    float* r = p + (size_t)row * CC;
    float v[4], s2 = 0.f, dummy = 0.f;
#pragma unroll
    for (int i = 0; i < 4; i++){ float x = r[t + 128*i]; v[i] = x; s2 += x*x; }
    block_reduce2_128(s2, dummy);
    float inv = 1.0f / fmaxf(sqrtf(s2), 1e-6f);
#pragma unroll
    for (int i = 0; i < 4; i++) r[t + 128*i] = v[i]*inv;
}

// ---------------- pad mask: |text row| sum <= 1e-6 ----------------
__global__ void pad_kernel(const float* __restrict__ text, int* __restrict__ pad){
    int row = blockIdx.x, t = threadIdx.x;
    const float* r = text + (size_t)row * CC;
    float s = 0.f, dummy = 0.f;
#pragma unroll
    for (int i = 0; i < 4; i++) s += fabsf(r[t + 128*i]);
    block_reduce2_128(s, dummy);
    if (t == 0) pad[row] = (s <= 1e-6f) ? 1 : 0;
}

// ---------------- tiled SGEMM: C = A[MxK] @ W[KxN] + bias, opt GELU / residual ----------------
template<bool GELU, bool RES>
__global__ __launch_bounds__(256) void gemm128(
    const float* __restrict__ A, const float* __restrict__ W,
    const float* __restrict__ bias, const float* __restrict__ res,
    float* __restrict__ Cout, int M, int N, int K)
{
    __shared__ float As[8][128];
    __shared__ float Bs[8][128];
    int tid = threadIdx.x;
    int rowBase = blockIdx.y * 128;
    int colBase = blockIdx.x * 128;
    int aRow = tid >> 1;
    int aK4  = (tid & 1) << 2;
    int bRow = tid >> 5;
    int bCol = (tid & 31) << 2;
    int tx = tid & 15, ty = tid >> 4;
    float acc[8][8];
#pragma unroll
    for (int i = 0; i < 8; i++)
#pragma unroll
        for (int j = 0; j < 8; j++) acc[i][j] = 0.f;

    bool aValid = (rowBase + aRow) < M;
    const float* aPtr = A + (size_t)(rowBase + aRow) * K + aK4;
    const float* bPtr = W + (size_t)bRow * N + colBase + bCol;

    for (int k0 = 0; k0 < K; k0 += 8){
        float4 av = aValid ? *(const float4*)(aPtr + k0) : make_float4(0.f,0.f,0.f,0.f);
        As[aK4+0][aRow] = av.x; As[aK4+1][aRow] = av.y;
        As[aK4+2][aRow] = av.z; As[aK4+3][aRow] = av.w;
        *(float4*)&Bs[bRow][bCol] = *(const float4*)(bPtr + (size_t)k0 * N);
        __syncthreads();
#pragma unroll
        for (int kk = 0; kk < 8; kk++){
            float4 m0 = *(const float4*)&As[kk][ty*8];
            float4 m1 = *(const float4*)&As[kk][ty*8+4];
            float4 n0 = *(const float4*)&Bs[kk][tx*8];
            float4 n1 = *(const float4*)&Bs[kk][tx*8+4];
            float rm[8] = {m0.x,m0.y,m0.z,m0.w,m1.x,m1.y,m1.z,m1.w};
            float rn[8] = {n0.x,n0.y,n0.z,n0.w,n1.x,n1.y,n1.z,n1.w};
#pragma unroll
            for (int i = 0; i < 8; i++)
#pragma unroll
                for (int j = 0; j < 8; j++)
                    acc[i][j] = fmaf(rm[i], rn[j], acc[i][j]);
        }
        __syncthreads();
    }

#pragma unroll
    for (int i = 0; i < 8; i++){
        int r = rowBase + ty*8 + i;
        if (r >= M) continue;
#pragma unroll
        for (int j = 0; j < 8; j += 4){
            int c = colBase + tx*8 + j;
            float4 bbv = *(const float4*)&bias[c];
            float4 v = make_float4(acc[i][j]   + bbv.x, acc[i][j+1] + bbv.y,
                                   acc[i][j+2] + bbv.z, acc[i][j+3] + bbv.w);
            if (GELU){
                v.x = gelu_exact(v.x); v.y = gelu_exact(v.y);
                v.z = gelu_exact(v.z); v.w = gelu_exact(v.w);
            }
            if (RES){
                float4 rv = *(const float4*)&res[(size_t)r*N + c];
                v.x += rv.x; v.y += rv.y; v.z += rv.z; v.w += rv.w;
            }
            *(float4*)&Cout[(size_t)r*N + c] = v;
        }
    }
}

// ---------------- fused attention: per (b, h, 32-row chunk) ----------------
// sim -> geo log bias -> pad mask -> top-3 threshold -> softmax -> conf -> attn@V
__global__ __launch_bounds__(256) void attn_kernel(
    const float* __restrict__ qf, const float* __restrict__ kf, const float* __restrict__ vf,
    const float* __restrict__ geo, const int* __restrict__ pad,
    const float* __restrict__ ls_p,
    float* __restrict__ aligned, float* __restrict__ conf_out)
{
    __shared__ float ks[TT*65];
    __shared__ float vs[TT*65];
    __shared__ float qs[32*64];
    __shared__ int   pads[TT];
    const int b = blockIdx.z, h = blockIdx.y;
    const int n0 = blockIdx.x << 5;
    const int tid = threadIdx.x;

    for (int idx = tid; idx < TT*64; idx += 256){
        int t = idx >> 6, d = idx & 63;
        size_t go = ((size_t)(b*TT + t)) * CC + h*DH64 + d;
        ks[t*65+d] = kf[go];
        vs[t*65+d] = vf[go];
    }
    for (int idx = tid; idx < 32*64; idx += 256){
        int r = idx >> 6;
        qs[idx] = qf[((size_t)(b*NSP + n0 + r))*CC + h*DH64 + (idx & 63)];
    }
    if (tid < TT) pads[tid] = pad[b*TT + tid];
    __syncthreads();

    float lsv   = fminf(fmaxf(ls_p[0], -2.0f), 2.0f);
    float scale = expf(lsv) * 0.125f;   // / sqrt(64)
    const int warp = tid >> 5, lane = tid & 31;
    const float NEG = -INFINITY;
    const unsigned FULL = 0xffffffffu;

    for (int rr = 0; rr < 4; rr++){
        int r = (warp << 2) + rr;
        int n = n0 + r;
        float geo_v = fminf(fmaxf(geo[b*NSP + n], 0.3f), 1.0f);
        float logg  = logf(geo_v);

        int  t0 = lane, t1 = lane + 32;
        bool v2 = (lane < 13);
        int  t2 = v2 ? lane + 64 : lane;

        float d0 = 0.f, d1 = 0.f, d2 = 0.f;
#pragma unroll
        for (int dd = 0; dd < 64; dd++){
            float qv = qs[(r << 6) + dd];
            d0 = fmaf(qv, ks[t0*65+dd], d0);
            d1 = fmaf(qv, ks[t1*65+dd], d1);
            d2 = fmaf(qv, ks[t2*65+dd], d2);
        }
        float s0 = pads[t0] ? NEG : fmaf(d0, scale, logg);
        float s1 = pads[t1] ? NEG : fmaf(d1, scale, logg);
        float s2 = (v2 && !pads[t2]) ? fmaf(d2, scale, logg) : NEG;

        // local sort desc of (a,bm,cm)
        float a = s0, bm = s1, cm = s2, tmp;
        if (a < bm){ tmp=a; a=bm; bm=tmp; }
        if (a < cm){ tmp=a; a=cm; cm=tmp; }
        if (bm < cm){ tmp=bm; bm=cm; cm=tmp; }
        // warp butterfly merge of sorted top-3 triples
#pragma unroll
        for (int off = 16; off > 0; off >>= 1){
            float a2 = __shfl_xor_sync(FULL, a,  off);
            float b2 = __shfl_xor_sync(FULL, bm, off);
            float c2 = __shfl_xor_sync(FULL, cm, off);
            float o0, o1, o2;
            if (a >= a2){
                o0 = a;
                if (bm >= a2){ o1 = bm; o2 = fmaxf(cm, a2); }
                else         { o1 = a2; o2 = fmaxf(bm, b2); }
            } else {
                o0 = a2;
                if (b2 >= a){ o1 = b2; o2 = fmaxf(c2, a); }
                else        { o1 = a;  o2 = fmaxf(bm, b2); }
            }
            a = o0; bm = o1; cm = o2;
        }
        float thr = cm, maxv = a;

        float e0 = (s0 >= thr && s0 != NEG) ? expf(s0 - maxv) : 0.f;
        float e1 = (s1 >= thr && s1 != NEG) ? expf(s1 - maxv) : 0.f;
        float e2 = (s2 >= thr && s2 != NEG) ? expf(s2 - maxv) : 0.f;

        float sum = warp_sum(e0 + e1 + e2);
        float cnt = warp_sum((e0 > 0.f ? 1.f : 0.f) + (e1 > 0.f ? 1.f : 0.f) + (e2 > 0.f ? 1.f : 0.f));
        float inv = sum > 0.f ? 1.f / sum : 0.f;
        float a0 = e0*inv, a1 = e1*inv, a2v = e2*inv;

        float mp = warp_max(fmaxf(a0, fmaxf(a1, a2v)));
        float le = 0.f;
        { float p = fmaxf(a0, 1e-8f); le -= p*logf(p); }
        { float p = fmaxf(a1, 1e-8f); le -= p*logf(p); }
        if (v2){ float p = fmaxf(a2v, 1e-8f); le -= p*logf(p); }
        le = warp_sum(le);
        float teff = fmaxf(cnt, 2.0f);
        float ent  = fmaxf(le / logf(teff), 0.f);
        float conf = fminf(fmaxf(mp * (1.f - ent), 0.f), 1.f);
        if (lane == 0) conf_out[((size_t)(b*NSP + n))*HH8 + h] = conf;

        // output: attn @ V (weights broadcast via shuffle)
        float acc0 = 0.f, acc1 = 0.f;
#pragma unroll
        for (int t = 0; t < TT; t++){
            float wgt = __shfl_sync(FULL, (t < 32) ? a0 : ((t < 64) ? a1 : a2v), t & 31);
            acc0 = fmaf(wgt, vs[t*65 + lane],      acc0);
            acc1 = fmaf(wgt, vs[t*65 + 32 + lane], acc1);
        }
        size_t ob = ((size_t)(b*NSP + n))*CC + h*DH64;
        aligned[ob + lane]      = acc0;
        aligned[ob + 32 + lane] = acc1;
    }
}

// ---------------- combine: y = x + alpha*gate*o_scaled; then LN2 -> h ----------------
__global__ void combine_ln2_kernel(
    const float* __restrict__ x, const float* __restrict__ o, const float* __restrict__ g,
    const float* __restrict__ geo, const float* __restrict__ conf,
    const float* __restrict__ alpha_p,
    const float* __restrict__ w, const float* __restrict__ b,
    float* __restrict__ y, float* __restrict__ h)
{
    int row = blockIdx.x, t = threadIdx.x;
    float geo_v = fminf(fmaxf(geo[row], 0.3f), 1.0f);
    const float* cp = conf + (size_t)row*HH8;
    float cf = 0.f;
#pragma unroll
    for (int i = 0; i < 8; i++) cf += cp[i];
    cf *= 0.125f;
    cf = fminf(fmaxf(cf, 0.f), 1.f);
    float cs = 0.35f + 0.65f * cf;
    float al = alpha_p[0];
    size_t base = (size_t)row * CC;

    float vy[4], s = 0.f, s2 = 0.f;
#pragma unroll
    for (int i = 0; i < 4; i++){
        int c = t + 128*i;
        float xv = x[base + c];
        float ov = o[base + c] * cs;
        float gv = geo_v / (1.0f + expf(-g[base + c]));
        float yy = xv + al * gv * ov;
        vy[i] = yy; s += yy; s2 += yy*yy;
    }
    block_reduce2_128(s, s2);
    float mu  = s  * (1.0f/512.0f);
    float var = s2 * (1.0f/512.0f) - mu*mu;
    float rs  = rsqrtf(var + 1e-5f);
#pragma unroll
    for (int i = 0; i < 4; i++){
        int c = t + 128*i;
        y[base + c] = vy[i];
        h[base + c] = (vy[i]-mu)*rs*w[c] + b[c];
    }
}

// ---------------- launch ----------------
extern "C" void kernel_launch(void* const* d_in, const int* in_sizes, int n_in,
                              void* d_out, int out_size)
{
    const float* visual = (const float*)d_in[0];
    const float* text   = (const float*)d_in[1];
    const float* geo    = (const float*)d_in[2];
    const float* ln1w = (const float*)d_in[3];
    const float* ln1b = (const float*)d_in[4];
    const float* wq = (const float*)d_in[5];
    const float* bq = (const float*)d_in[6];
    const float* wk = (const float*)d_in[7];
    const float* bk = (const float*)d_in[8];
    const float* wv = (const float*)d_in[9];
    const float* bv = (const float*)d_in[10];
    const float* wo = (const float*)d_in[11];
    const float* bo = (const float*)d_in[12];
    const float* gate_w = (const float*)d_in[13];
    const float* gate_b = (const float*)d_in[14];
    const float* logit_scale = (const float*)d_in[15];
    const float* alpha = (const float*)d_in[16];
    const float* ln2w = (const float*)d_in[17];
    const float* ln2b = (const float*)d_in[18];
    const float* w1 = (const float*)d_in[19];
    const float* b1 = (const float*)d_in[20];
    const float* w2 = (const float*)d_in[21];
    const float* b2 = (const float*)d_in[22];
    float* out = (float*)d_out;

    float *px, *pq, *pkf, *pvf, *pal, *po, *pg, *pcf, *py, *ph, *pf1;
    int* ppad;
    cudaGetSymbolAddress((void**)&px,  g_x);
    cudaGetSymbolAddress((void**)&pq,  g_q);
    cudaGetSymbolAddress((void**)&pkf, g_kf);
    cudaGetSymbolAddress((void**)&pvf, g_vf);
    cudaGetSymbolAddress((void**)&ppad,g_pad);
    cudaGetSymbolAddress((void**)&pal, g_al);
    cudaGetSymbolAddress((void**)&po,  g_o);
    cudaGetSymbolAddress((void**)&pg,  g_g);
    cudaGetSymbolAddress((void**)&pcf, g_cf);
    cudaGetSymbolAddress((void**)&py,  g_y);
    cudaGetSymbolAddress((void**)&ph,  g_h);
    cudaGetSymbolAddress((void**)&pf1, g_f1);

    // 1) x = LN1(visual)
    ln_kernel<<<MR, 128>>>(visual, ln1w, ln1b, px);
    // 2) q = x@wq + bq ; L2-normalize rows
    gemm128<false,false><<<dim3(4,256), 256>>>(px, wq, bq, nullptr, pq, MR, CC, CC);
    l2norm_kernel<<<MR, 128>>>(pq);
    // 3) k = text@wk + bk (L2-normed); v = text@wv + bv
    gemm128<false,false><<<dim3(4,5), 256>>>(text, wk, bk, nullptr, pkf, MT, CC, CC);
    l2norm_kernel<<<MT, 128>>>(pkf);
    gemm128<false,false><<<dim3(4,5), 256>>>(text, wv, bv, nullptr, pvf, MT, CC, CC);
    // 4) pad mask
    pad_kernel<<<MT, 128>>>(text, ppad);
    // 5) fused attention (sim, top-3, softmax, conf, attn@V)
    attn_kernel<<<dim3(NSP/32, HH8, BB), 256>>>(pq, pkf, pvf, geo, ppad, logit_scale, pal, pcf);
    // 6) o = aligned@wo + bo ; gate = x@gate_w + gate_b
    gemm128<false,false><<<dim3(4,256), 256>>>(pal, wo, bo, nullptr, po, MR, CC, CC);
    gemm128<false,false><<<dim3(4,256), 256>>>(px, gate_w, gate_b, nullptr, pg, MR, CC, CC);
    // 7) y = x + alpha*gate*(o*conf_scale) ; h = LN2(y)
    combine_ln2_kernel<<<MR, 128>>>(px, po, pg, geo, pcf, alpha, ln2w, ln2b, py, ph);
    // 8) ffn
    gemm128<true,false><<<dim3(16,256), 256>>>(ph, w1, b1, nullptr, pf1, MR, FFN, CC);
    gemm128<false,true><<<dim3(4,256), 256>>>(pf1, w2, b2, py, out, MR, CC, FFN);
}

// round 11
// speedup vs baseline: 1.0018x; 1.0018x over previous
#include <cuda_runtime.h>
#include <cuda_bf16.h>
#include <math.h>

// ---------------- problem constants ----------------
#define BB   8
#define HSZ  64
#define WSZ  64
#define NSP  (HSZ*WSZ)          // 4096 spatial positions per batch
#define MR   (BB*NSP)           // 32768 rows
#define CC   512
#define TT   77
#define MT   (BB*TT)            // 616 text rows
#define HH8  8
#define DH64 64
#define FFN  2048

// ---------------- scratch (device globals; no runtime alloc) ----------------
__device__ float g_x  [(size_t)MR*CC];   // LN1 output
__device__ float g_q  [(size_t)MR*CC];   // q projection (l2-normed in place)
__device__ float g_kf [(size_t)MT*CC];
__device__ float g_vf [(size_t)MT*CC];
__device__ int   g_pad[MT];
__device__ float g_al [(size_t)MR*CC];   // attention output (pre-wo)
__device__ float g_o  [(size_t)MR*CC];   // aligned@wo + bo
__device__ float g_g  [(size_t)MR*CC];   // gate linear
__device__ float g_cf [(size_t)MR*HH8];  // per-head conf
__device__ float g_y  [(size_t)MR*CC];   // residual stream
__device__ float g_h  [(size_t)MR*CC];   // LN2 output
__device__ float g_f1 [(size_t)MR*FFN];  // ffn intermediate

// ---------------- helpers ----------------
__device__ __forceinline__ float warp_sum(float v){
#pragma unroll
    for (int o = 16; o > 0; o >>= 1) v += __shfl_xor_sync(0xffffffffu, v, o);
    return v;
}
__device__ __forceinline__ float warp_max(float v){
#pragma unroll
    for (int o = 16; o > 0; o >>= 1) v = fmaxf(v, __shfl_xor_sync(0xffffffffu, v, o));
    return v;
}
__device__ __forceinline__ float gelu_exact(float x){
    return 0.5f * x * (1.0f + erff(x * 0.70710678118654752440f));
}

// block of 128 threads: reduce two partial sums to totals (all threads get result)
__device__ __forceinline__ void block_reduce2_128(float& s, float& s2){
    __shared__ float sh[8];
    s  = warp_sum(s);
    s2 = warp_sum(s2);
    int t = threadIdx.x;
    if ((t & 31) == 0){ sh[t >> 5] = s; sh[4 + (t >> 5)] = s2; }
    __syncthreads();
    s  = sh[0] + sh[1] + sh[2] + sh[3];
    s2 = sh[4] + sh[5] + sh[6] + sh[7];
}

// ---------------- LayerNorm over 512 (one block per row, 128 threads) ----------------
__global__ void ln_kernel(const float* __restrict__ in, const float* __restrict__ w,
                          const float* __restrict__ b, float* __restrict__ out){
    int row = blockIdx.x, t = threadIdx.x;
    const float* p = in + (size_t)row * CC;
    float v[4], s = 0.f, s2 = 0.f;
#pragma unroll
    for (int i = 0; i < 4; i++){ float x = p[t + 128*i]; v[i] = x; s += x; s2 += x*x; }
    block_reduce2_128(s, s2);
    float mu  = s  * (1.0f/512.0f);
    float var = s2 * (1.0f/512.0f) - mu*mu;
    float rs  = rsqrtf(var + 1e-5f);
#pragma unroll
    for (int i = 0; i < 4; i++){
        int c = t + 128*i;
        out[(size_t)row*CC + c] = (v[i]-mu)*rs*w[c] + b[c];
    }
}

// ---------------- row-wise L2 normalize (in place) ----------------
__global__ void l2norm_kernel(float* __restrict__ p){
    int row = blockIdx.x, t = threadIdx.x;
    float* r = p + (size_t)row * CC;
    float v[4], s2 = 0.f, dummy = 0.f;
#pragma unroll
    for (int i = 0; i < 4; i++){ float x = r[t + 128*i]; v[i] = x; s2 += x*x; }
    block_reduce2_128(s2, dummy);
    float inv = 1.0f / fmaxf(sqrtf(s2), 1e-6f);
#pragma unroll
    for (int i = 0; i < 4; i++) r[t + 128*i] = v[i]*inv;
}

// ---------------- pad mask: |text row| sum <= 1e-6 ----------------
__global__ void pad_kernel(const float* __restrict__ text, int* __restrict__ pad){
    int row = blockIdx.x, t = threadIdx.x;
    const float* r = text + (size_t)row * CC;
    float s = 0.f, dummy = 0.f;
#pragma unroll
    for (int i = 0; i < 4; i++) s += fabsf(r[t + 128*i]);
    block_reduce2_128(s, dummy);
    if (t == 0) pad[row] = (s <= 1e-6f) ? 1 : 0;
}

// ---------------- tiled SGEMM: C = A[MxK] @ W[KxN] + bias, opt GELU / residual ----------------
template<bool GELU, bool RES>
__global__ __launch_bounds__(256) void gemm128(
    const float* __restrict__ A, const float* __restrict__ W,
    const float* __restrict__ bias, const float* __restrict__ res,
    float* __restrict__ Cout, int M, int N, int K)
{
    __shared__ float As[8][128];
    __shared__ float Bs[8][128];
    int tid = threadIdx.x;
    int rowBase = blockIdx.y * 128;
    int colBase = blockIdx.x * 128;
    int aRow = tid >> 1;
    int aK4  = (tid & 1) << 2;
    int bRow = tid >> 5;
    int bCol = (tid & 31) << 2;
    int tx = tid & 15, ty = tid >> 4;
    float acc[8][8];
#pragma unroll
    for (int i = 0; i < 8; i++)
#pragma unroll
        for (int j = 0; j < 8; j++) acc[i][j] = 0.f;

    bool aValid = (rowBase + aRow) < M;
    const float* aPtr = A + (size_t)(rowBase + aRow) * K + aK4;
    const float* bPtr = W + (size_t)bRow * N + colBase + bCol;

    for (int k0 = 0; k0 < K; k0 += 8){
        float4 av = aValid ? *(const float4*)(aPtr + k0) : make_float4(0.f,0.f,0.f,0.f);
        As[aK4+0][aRow] = av.x; As[aK4+1][aRow] = av.y;
        As[aK4+2][aRow] = av.z; As[aK4+3][aRow] = av.w;
        *(float4*)&Bs[bRow][bCol] = *(const float4*)(bPtr + (size_t)k0 * N);
        __syncthreads();
#pragma unroll
        for (int kk = 0; kk < 8; kk++){
            float4 m0 = *(const float4*)&As[kk][ty*8];
            float4 m1 = *(const float4*)&As[kk][ty*8+4];
            float4 n0 = *(const float4*)&Bs[kk][tx*8];
            float4 n1 = *(const float4*)&Bs[kk][tx*8+4];
            float rm[8] = {m0.x,m0.y,m0.z,m0.w,m1.x,m1.y,m1.z,m1.w};
            float rn[8] = {n0.x,n0.y,n0.z,n0.w,n1.x,n1.y,n1.z,n1.w};
#pragma unroll
            for (int i = 0; i < 8; i++)
#pragma unroll
                for (int j = 0; j < 8; j++)
                    acc[i][j] = fmaf(rm[i], rn[j], acc[i][j]);
        }
        __syncthreads();
    }

#pragma unroll
    for (int i = 0; i < 8; i++){
        int r = rowBase + ty*8 + i;
        if (r >= M) continue;
#pragma unroll
        for (int j = 0; j < 8; j += 4){
            int c = colBase + tx*8 + j;
            float4 bbv = *(const float4*)&bias[c];
            float4 v = make_float4(acc[i][j]   + bbv.x, acc[i][j+1] + bbv.y,
                                   acc[i][j+2] + bbv.z, acc[i][j+3] + bbv.w);
            if (GELU){
                v.x = gelu_exact(v.x); v.y = gelu_exact(v.y);
                v.z = gelu_exact(v.z); v.w = gelu_exact(v.w);
            }
            if (RES){
                float4 rv = *(const float4*)&res[(size_t)r*N + c];
                v.x += rv.x; v.y += rv.y; v.z += rv.z; v.w += rv.w;
            }
            *(float4*)&Cout[(size_t)r*N + c] = v;
        }
    }
}

// ---------------- fused attention: per (b, h, 32-row chunk) ----------------
// sim -> geo log bias -> pad mask -> top-3 threshold -> softmax -> conf -> attn@V
__global__ __launch_bounds__(256) void attn_kernel(
    const float* __restrict__ qf, const float* __restrict__ kf, const float* __restrict__ vf,
    const float* __restrict__ geo, const int* __restrict__ pad,
    const float* __restrict__ ls_p,
    float* __restrict__ aligned, float* __restrict__ conf_out)
{
    __shared__ float ks[TT*65];
    __shared__ float vs[TT*65];
    __shared__ float qs[32*64];
    __shared__ int   pads[TT];
    const int b = blockIdx.z, h = blockIdx.y;
    const int n0 = blockIdx.x << 5;
    const int tid = threadIdx.x;

    for (int idx = tid; idx < TT*64; idx += 256){
        int t = idx >> 6, d = idx & 63;
        size_t go = ((size_t)(b*TT + t)) * CC + h*DH64 + d;
        ks[t*65+d] = kf[go];
        vs[t*65+d] = vf[go];
    }
    for (int idx = tid; idx < 32*64; idx += 256){
        int r = idx >> 6;
        qs[idx] = qf[((size_t)(b*NSP + n0 + r))*CC + h*DH64 + (idx & 63)];
    }
    if (tid < TT) pads[tid] = pad[b*TT + tid];
    __syncthreads();

    float lsv   = fminf(fmaxf(ls_p[0], -2.0f), 2.0f);
    float scale = expf(lsv) * 0.125f;   // / sqrt(64)
    const int warp = tid >> 5, lane = tid & 31;
    const float NEG = -INFINITY;
    const unsigned FULL = 0xffffffffu;

    for (int rr = 0; rr < 4; rr++){
        int r = (warp << 2) + rr;
        int n = n0 + r;
        float geo_v = fminf(fmaxf(geo[b*NSP + n], 0.3f), 1.0f);
        float logg  = logf(geo_v);

        int  t0 = lane, t1 = lane + 32;
        bool v2 = (lane < 13);
        int  t2 = v2 ? lane + 64 : lane;

        float d0 = 0.f, d1 = 0.f, d2 = 0.f;
#pragma unroll
        for (int dd = 0; dd < 64; dd++){
            float qv = qs[(r << 6) + dd];
            d0 = fmaf(qv, ks[t0*65+dd], d0);
            d1 = fmaf(qv, ks[t1*65+dd], d1);
            d2 = fmaf(qv, ks[t2*65+dd], d2);
        }
        float s0 = pads[t0] ? NEG : fmaf(d0, scale, logg);
        float s1 = pads[t1] ? NEG : fmaf(d1, scale, logg);
        float s2 = (v2 && !pads[t2]) ? fmaf(d2, scale, logg) : NEG;

        // local sort desc of (a,bm,cm)
        float a = s0, bm = s1, cm = s2, tmp;
        if (a < bm){ tmp=a; a=bm; bm=tmp; }
        if (a < cm){ tmp=a; a=cm; cm=tmp; }
        if (bm < cm){ tmp=bm; bm=cm; cm=tmp; }
        // warp butterfly merge of sorted top-3 triples
#pragma unroll
        for (int off = 16; off > 0; off >>= 1){
            float a2 = __shfl_xor_sync(FULL, a,  off);
            float b2 = __shfl_xor_sync(FULL, bm, off);
            float c2 = __shfl_xor_sync(FULL, cm, off);
            float o0, o1, o2;
            if (a >= a2){
                o0 = a;
                if (bm >= a2){ o1 = bm; o2 = fmaxf(cm, a2); }
                else         { o1 = a2; o2 = fmaxf(bm, b2); }
            } else {
                o0 = a2;
                if (b2 >= a){ o1 = b2; o2 = fmaxf(c2, a); }
                else        { o1 = a;  o2 = fmaxf(bm, b2); }
            }
            a = o0; bm = o1; cm = o2;
        }
        float thr = cm, maxv = a;

        float e0 = (s0 >= thr && s0 != NEG) ? expf(s0 - maxv) : 0.f;
        float e1 = (s1 >= thr && s1 != NEG) ? expf(s1 - maxv) : 0.f;
        float e2 = (s2 >= thr && s2 != NEG) ? expf(s2 - maxv) : 0.f;

        float sum = warp_sum(e0 + e1 + e2);
        float cnt = warp_sum((e0 > 0.f ? 1.f : 0.f) + (e1 > 0.f ? 1.f : 0.f) + (e2 > 0.f ? 1.f : 0.f));
        float inv = sum > 0.f ? 1.f / sum : 0.f;
        float a0 = e0*inv, a1 = e1*inv, a2v = e2*inv;

        float mp = warp_max(fmaxf(a0, fmaxf(a1, a2v)));
        float le = 0.f;
        { float p = fmaxf(a0, 1e-8f); le -= p*logf(p); }
        { float p = fmaxf(a1, 1e-8f); le -= p*logf(p); }
        if (v2){ float p = fmaxf(a2v, 1e-8f); le -= p*logf(p); }
        le = warp_sum(le);
        float teff = fmaxf(cnt, 2.0f);
        float ent  = fmaxf(le / logf(teff), 0.f);
        float conf = fminf(fmaxf(mp * (1.f - ent), 0.f), 1.f);
        if (lane == 0) conf_out[((size_t)(b*NSP + n))*HH8 + h] = conf;

        // output: attn @ V (weights broadcast via shuffle)
        float acc0 = 0.f, acc1 = 0.f;
#pragma unroll
        for (int t = 0; t < TT; t++){
            float wgt = __shfl_sync(FULL, (t < 32) ? a0 : ((t < 64) ? a1 : a2v), t & 31);
            acc0 = fmaf(wgt, vs[t*65 + lane],      acc0);
            acc1 = fmaf(wgt, vs[t*65 + 32 + lane], acc1);
        }
        size_t ob = ((size_t)(b*NSP + n))*CC + h*DH64;
        aligned[ob + lane]      = acc0;
        aligned[ob + 32 + lane] = acc1;
    }
}

// ---------------- combine: y = x + alpha*gate*o_scaled; then LN2 -> h ----------------
__global__ void combine_ln2_kernel(
    const float* __restrict__ x, const float* __restrict__ o, const float* __restrict__ g,
    const float* __restrict__ geo, const float* __restrict__ conf,
    const float* __restrict__ alpha_p,
    const float* __restrict__ w, const float* __restrict__ b,
    float* __restrict__ y, float* __restrict__ h)
{
    int row = blockIdx.x, t = threadIdx.x;
    float geo_v = fminf(fmaxf(geo[row], 0.3f), 1.0f);
    const float* cp = conf + (size_t)row*HH8;
    float cf = 0.f;
#pragma unroll
    for (int i = 0; i < 8; i++) cf += cp[i];
    cf *= 0.125f;
    cf = fminf(fmaxf(cf, 0.f), 1.f);
    float cs = 0.35f + 0.65f * cf;
    float al = alpha_p[0];
    size_t base = (size_t)row * CC;

    float vy[4], s = 0.f, s2 = 0.f;
#pragma unroll
    for (int i = 0; i < 4; i++){
        int c = t + 128*i;
        float xv = x[base + c];
        float ov = o[base + c] * cs;
        float gv = geo_v / (1.0f + expf(-g[base + c]));
        float yy = xv + al * gv * ov;
        vy[i] = yy; s += yy; s2 += yy*yy;
    }
    block_reduce2_128(s, s2);
    float mu  = s  * (1.0f/512.0f);
    float var = s2 * (1.0f/512.0f) - mu*mu;
    float rs  = rsqrtf(var + 1e-5f);
#pragma unroll
    for (int i = 0; i < 4; i++){
        int c = t + 128*i;
        y[base + c] = vy[i];
        h[base + c] = (vy[i]-mu)*rs*w[c] + b[c];
    }
}

// ---------------- launch ----------------
extern "C" void kernel_launch(void* const* d_in, const int* in_sizes, int n_in,
                              void* d_out, int out_size)
{
    const float* visual = (const float*)d_in[0];
    const float* text   = (const float*)d_in[1];
    const float* geo    = (const float*)d_in[2];
    const float* ln1w = (const float*)d_in[3];
    const float* ln1b = (const float*)d_in[4];
    const float* wq = (const float*)d_in[5];
    const float* bq = (const float*)d_in[6];
    const float* wk = (const float*)d_in[7];
    const float* bk = (const float*)d_in[8];
    const float* wv = (const float*)d_in[9];
    const float* bv = (const float*)d_in[10];
    const float* wo = (const float*)d_in[11];
    const float* bo = (const float*)d_in[12];
    const float* gate_w = (const float*)d_in[13];
    const float* gate_b = (const float*)d_in[14];
    const float* logit_scale = (const float*)d_in[15];
    const float* alpha = (const float*)d_in[16];
    const float* ln2w = (const float*)d_in[17];
    const float* ln2b = (const float*)d_in[18];
    const float* w1 = (const float*)d_in[19];
    const float* b1 = (const float*)d_in[20];
    const float* w2 = (const float*)d_in[21];
    const float* b2 = (const float*)d_in[22];
    float* out = (float*)d_out;

    float *px, *pq, *pkf, *pvf, *pal, *po, *pg, *pcf, *py, *ph, *pf1;
    int* ppad;
    cudaGetSymbolAddress((void**)&px,  g_x);
    cudaGetSymbolAddress((void**)&pq,  g_q);
    cudaGetSymbolAddress((void**)&pkf, g_kf);
    cudaGetSymbolAddress((void**)&pvf, g_vf);
    cudaGetSymbolAddress((void**)&ppad,g_pad);
    cudaGetSymbolAddress((void**)&pal, g_al);
    cudaGetSymbolAddress((void**)&po,  g_o);
    cudaGetSymbolAddress((void**)&pg,  g_g);
    cudaGetSymbolAddress((void**)&pcf, g_cf);
    cudaGetSymbolAddress((void**)&py,  g_y);
    cudaGetSymbolAddress((void**)&ph,  g_h);
    cudaGetSymbolAddress((void**)&pf1, g_f1);

    // 1) x = LN1(visual)
    ln_kernel<<<MR, 128>>>(visual, ln1w, ln1b, px);
    // 2) q = x@wq + bq ; L2-normalize rows
    gemm128<false,false><<<dim3(4,256), 256>>>(px, wq, bq, nullptr, pq, MR, CC, CC);
    l2norm_kernel<<<MR, 128>>>(pq);
    // 3) k = text@wk + bk (L2-normed); v = text@wv + bv
    gemm128<false,false><<<dim3(4,5), 256>>>(text, wk, bk, nullptr, pkf, MT, CC, CC);
    l2norm_kernel<<<MT, 128>>>(pkf);
    gemm128<false,false><<<dim3(4,5), 256>>>(text, wv, bv, nullptr, pvf, MT, CC, CC);
    // 4) pad mask
    pad_kernel<<<MT, 128>>>(text, ppad);
    // 5) fused attention (sim, top-3, softmax, conf, attn@V)
    attn_kernel<<<dim3(NSP/32, HH8, BB), 256>>>(pq, pkf, pvf, geo, ppad, logit_scale, pal, pcf);
    // 6) o = aligned@wo + bo ; gate = x@gate_w + gate_b
    gemm128<false,false><<<dim3(4,256), 256>>>(pal, wo, bo, nullptr, po, MR, CC, CC);
    gemm128<false,false><<<dim3(4,256), 256>>>(px, gate_w, gate_b, nullptr, pg, MR, CC, CC);
    // 7) y = x + alpha*gate*(o*conf_scale) ; h = LN2(y)
    combine_ln2_kernel<<<MR, 128>>>(px, po, pg, geo, pcf, alpha, ln2w, ln2b, py, ph);
    // 8) ffn
    gemm128<true,false><<<dim3(16,256), 256>>>(ph, w1, b1, nullptr, pf1, MR, FFN, CC);
    gemm128<false,true><<<dim3(4,256), 256>>>(pf1, w2, b2, py, out, MR, CC, FFN);
}